// round 1
// baseline (speedup 1.0000x reference)
#include <cuda_runtime.h>

// Problem constants
#define BB 8
#define HH 4
#define LL 2048
#define DD 128
#define DKK 32
#define NEGV (-1e30f)
#define SCALE 0.17677669529663689f   // 1/sqrt(32)

// Scratch (device globals — no allocation allowed)
__device__ float g_q[BB*HH*LL*DKK];     // (b,h,l,dk)
__device__ float g_k[BB*HH*LL*DKK];
__device__ float g_v[BB*HH*LL*DKK];
__device__ float g_head[BB*LL*DD];      // (b,l, h*32+dk)

// ---------------------------------------------------------------------------
// Kernel A: fused QKV projection.
// C[M=16384, N=384] = XT[M,128] @ Wcat[128,384], per-batch.
// Block: 64(l) x 64(o) tile, 256 threads, 4x4 micro-tile.
// ---------------------------------------------------------------------------
__global__ __launch_bounds__(256) void qkv_kernel(
    const float* __restrict__ x,
    const float* __restrict__ Wq,
    const float* __restrict__ Wk,
    const float* __restrict__ Wv)
{
    __shared__ __align__(16) float As[16][68];
    __shared__ __align__(16) float Bs[16][68];

    const int b  = blockIdx.z;
    const int l0 = blockIdx.y * 64;
    const int n0 = blockIdx.x * 64;
    const int t  = threadIdx.x;
    const int ty = t >> 4;
    const int tx = t & 15;

    float acc[4][4] = {};

    for (int k0 = 0; k0 < DD; k0 += 16) {
        // A tile: As[kk][m] = x[b][k0+kk][l0+m]  (coalesced along l)
        {
            int row = t >> 4;
            int c4  = t & 15;
            const float* src = x + ((b*DD + k0 + row) * LL + l0 + c4*4);
            float4 v4 = *reinterpret_cast<const float4*>(src);
            *reinterpret_cast<float4*>(&As[row][c4*4]) = v4;
        }
        // B tile: Bs[kk][oo] = Wcat[k0+kk][n0+oo]
        #pragma unroll
        for (int i = 0; i < 4; i++) {
            int e  = t + i*256;
            int kk = e >> 6;
            int oo = e & 63;
            int o  = n0 + oo;
            int mat = o >> 7;
            int h   = (o >> 5) & 3;
            int dk  = o & 31;
            const float* w = (mat == 0) ? Wq : ((mat == 1) ? Wk : Wv);
            Bs[kk][oo] = w[(h*DD + (k0+kk))*DKK + dk];
        }
        __syncthreads();
        #pragma unroll
        for (int kk = 0; kk < 16; kk++) {
            float4 a4 = *reinterpret_cast<float4*>(&As[kk][ty*4]);
            float4 b4 = *reinterpret_cast<float4*>(&Bs[kk][tx*4]);
            float av[4] = {a4.x, a4.y, a4.z, a4.w};
            float bv[4] = {b4.x, b4.y, b4.z, b4.w};
            #pragma unroll
            for (int i = 0; i < 4; i++)
                #pragma unroll
                for (int j = 0; j < 4; j++)
                    acc[i][j] += av[i] * bv[j];
        }
        __syncthreads();
    }

    // Store to g_q/g_k/g_v in (b,h,l,dk) layout
    #pragma unroll
    for (int i = 0; i < 4; i++) {
        int l = l0 + ty*4 + i;
        #pragma unroll
        for (int j = 0; j < 4; j++) {
            int o   = n0 + tx*4 + j;
            int mat = o >> 7;
            int h   = (o >> 5) & 3;
            int dk  = o & 31;
            float* dst = (mat == 0) ? g_q : ((mat == 1) ? g_k : g_v);
            dst[((b*HH + h)*LL + l)*DKK + dk] = acc[i][j];
        }
    }
}

// ---------------------------------------------------------------------------
// Kernel B: flash attention. One block = (b, h, 64-query tile).
// Streams 64-key tiles: S = Q K^T (4x4 micro-tiles), online softmax with
// shuffle row-reductions, P staged in smem, O accumulated in registers.
// ---------------------------------------------------------------------------
__global__ __launch_bounds__(256) void attn_kernel(const float* __restrict__ mask)
{
    __shared__ __align__(16) float Qs[DKK][68];   // [dk][r]
    __shared__ __align__(16) float Ks[DKK][68];   // [dk][c]
    __shared__ __align__(16) float Vs[64][36];    // [c][dk]
    __shared__ __align__(16) float Ps[64][68];    // [r][c]
    __shared__ float row_m[64], row_l[64], row_f[64], maskk[64];

    const int b  = blockIdx.z;
    const int h  = blockIdx.y;
    const int q0 = blockIdx.x * 64;
    const int t  = threadIdx.x;
    const int ty = t >> 4, tx = t & 15;   // S-phase mapping (16x16)
    const int ry = t >> 3, cx = t & 7;    // PV-phase mapping (32x8)

    const float* Qg = g_q + (b*HH + h)*LL*DKK;
    const float* Kg = g_k + (b*HH + h)*LL*DKK;
    const float* Vg = g_v + (b*HH + h)*LL*DKK;

    // Load Q tile transposed: Qs[dk][r]
    #pragma unroll
    for (int i = 0; i < 8; i++) {
        int e = t + i*256;
        int r = e >> 5, dk = e & 31;
        Qs[dk][r] = Qg[(q0 + r)*DKK + dk];
    }
    if (t < 64) { row_m[t] = -3e38f; row_l[t] = 0.0f; }

    float o_acc[2][4] = {};
    __syncthreads();

    for (int kt = 0; kt < LL/64; kt++) {
        const int c0 = kt * 64;
        // Load K (transposed) and V (natural), plus key mask
        #pragma unroll
        for (int i = 0; i < 8; i++) {
            int e = t + i*256;
            int r = e >> 5, dk = e & 31;
            float kv = Kg[(c0 + r)*DKK + dk];
            float vv = Vg[(c0 + r)*DKK + dk];
            Ks[dk][r] = kv;
            Vs[r][dk] = vv;
        }
        if (t < 64) maskk[t] = mask[b*LL + c0 + t];
        __syncthreads();

        // S = Q K^T  (raw dot, scale applied after)
        float acc[4][4] = {};
        #pragma unroll
        for (int dk = 0; dk < DKK; dk++) {
            float4 a4 = *reinterpret_cast<float4*>(&Qs[dk][ty*4]);
            float4 b4 = *reinterpret_cast<float4*>(&Ks[dk][tx*4]);
            float av[4] = {a4.x, a4.y, a4.z, a4.w};
            float bv[4] = {b4.x, b4.y, b4.z, b4.w};
            #pragma unroll
            for (int i = 0; i < 4; i++)
                #pragma unroll
                for (int j = 0; j < 4; j++)
                    acc[i][j] += av[i] * bv[j];
        }

        // Online softmax per row
        float mk[4];
        #pragma unroll
        for (int j = 0; j < 4; j++) mk[j] = maskk[tx*4 + j];

        #pragma unroll
        for (int i = 0; i < 4; i++) {
            int r = ty*4 + i;
            float s[4];
            float mloc = -3e38f;
            #pragma unroll
            for (int j = 0; j < 4; j++) {
                float sv = acc[i][j] * SCALE;
                if (mk[j] > 0.5f) sv = NEGV;   // key-masked -> exact NEG
                s[j] = sv;
                mloc = fmaxf(mloc, sv);
            }
            #pragma unroll
            for (int off = 1; off < 16; off <<= 1)
                mloc = fmaxf(mloc, __shfl_xor_sync(0xffffffffu, mloc, off));
            float mold = row_m[r];
            float mnew = fmaxf(mold, mloc);
            float f = __expf(mold - mnew);
            float p[4];
            float ssum = 0.0f;
            #pragma unroll
            for (int j = 0; j < 4; j++) {
                p[j] = __expf(s[j] - mnew);
                ssum += p[j];
            }
            #pragma unroll
            for (int off = 1; off < 16; off <<= 1)
                ssum += __shfl_xor_sync(0xffffffffu, ssum, off);
            if (tx == 0) {
                row_m[r] = mnew;
                row_l[r] = row_l[r] * f + ssum;
                row_f[r] = f;
            }
            *reinterpret_cast<float4*>(&Ps[r][tx*4]) =
                make_float4(p[0], p[1], p[2], p[3]);
        }
        __syncthreads();

        // O rescale + O += P V
        {
            float f0 = row_f[ry*2];
            float f1 = row_f[ry*2 + 1];
            #pragma unroll
            for (int j = 0; j < 4; j++) { o_acc[0][j] *= f0; o_acc[1][j] *= f1; }
        }
        #pragma unroll 4
        for (int k = 0; k < 64; k++) {
            float a0 = Ps[ry*2][k];
            float a1 = Ps[ry*2 + 1][k];
            float4 b4 = *reinterpret_cast<float4*>(&Vs[k][cx*4]);
            o_acc[0][0] += a0 * b4.x; o_acc[0][1] += a0 * b4.y;
            o_acc[0][2] += a0 * b4.z; o_acc[0][3] += a0 * b4.w;
            o_acc[1][0] += a1 * b4.x; o_acc[1][1] += a1 * b4.y;
            o_acc[1][2] += a1 * b4.z; o_acc[1][3] += a1 * b4.w;
        }
        __syncthreads();
    }

    // Epilogue: /l, * query-mask, write heads in (b, l, h*32+dk) layout
    #pragma unroll
    for (int i = 0; i < 2; i++) {
        int r  = ry*2 + i;
        int lq = q0 + r;
        float mq  = mask[b*LL + lq];          // reference: attn *= mask[q]
        float inv = mq / row_l[r];
        #pragma unroll
        for (int j = 0; j < 4; j++)
            g_head[(b*LL + lq)*DD + h*DKK + cx*4 + j] = o_acc[i][j] * inv;
    }
}

// ---------------------------------------------------------------------------
// Kernel C: output projection + transpose.
// out[b, n, l] = sum_e head[b, l, e] * Wo[e, n]
// ---------------------------------------------------------------------------
__global__ __launch_bounds__(256) void out_kernel(
    const float* __restrict__ Wo, float* __restrict__ out)
{
    __shared__ __align__(16) float As[16][68];
    __shared__ __align__(16) float Bs[16][68];
    __shared__ float Cs[64][65];

    const int b  = blockIdx.z;
    const int l0 = blockIdx.y * 64;
    const int n0 = blockIdx.x * 64;
    const int t  = threadIdx.x;
    const int ty = t >> 4, tx = t & 15;

    float acc[4][4] = {};

    for (int k0 = 0; k0 < DD; k0 += 16) {
        #pragma unroll
        for (int i = 0; i < 4; i++) {
            int e  = t + i*256;
            int kk = e & 15, m = e >> 4;
            As[kk][m] = g_head[(b*LL + l0 + m)*DD + k0 + kk];
        }
        #pragma unroll
        for (int i = 0; i < 4; i++) {
            int e  = t + i*256;
            int nn = e & 63, kk = e >> 6;
            Bs[kk][nn] = Wo[(k0 + kk)*DD + n0 + nn];
        }
        __syncthreads();
        #pragma unroll
        for (int kk = 0; kk < 16; kk++) {
            float4 a4 = *reinterpret_cast<float4*>(&As[kk][ty*4]);
            float4 b4 = *reinterpret_cast<float4*>(&Bs[kk][tx*4]);
            float av[4] = {a4.x, a4.y, a4.z, a4.w};
            float bv[4] = {b4.x, b4.y, b4.z, b4.w};
            #pragma unroll
            for (int i = 0; i < 4; i++)
                #pragma unroll
                for (int j = 0; j < 4; j++)
                    acc[i][j] += av[i] * bv[j];
        }
        __syncthreads();
    }

    // Stage through smem for coalesced (along l) store
    #pragma unroll
    for (int i = 0; i < 4; i++)
        #pragma unroll
        for (int j = 0; j < 4; j++)
            Cs[ty*4 + i][tx*4 + j] = acc[i][j];
    __syncthreads();
    #pragma unroll
    for (int i = 0; i < 16; i++) {
        int e  = t + i*256;
        int mm = e & 63, nn = e >> 6;
        out[(b*DD + n0 + nn)*LL + l0 + mm] = Cs[mm][nn];
    }
}

// ---------------------------------------------------------------------------
extern "C" void kernel_launch(void* const* d_in, const int* in_sizes, int n_in,
                              void* d_out, int out_size)
{
    const float* x    = (const float*)d_in[0];
    const float* mask = (const float*)d_in[1];
    const float* Wq   = (const float*)d_in[2];
    const float* Wk   = (const float*)d_in[3];
    const float* Wv   = (const float*)d_in[4];
    const float* Wo   = (const float*)d_in[5];
    float* out = (float*)d_out;

    dim3 gA(6, LL/64, BB);     // 384/64 x 32 x 8
    qkv_kernel<<<gA, 256>>>(x, Wq, Wk, Wv);

    dim3 gB(LL/64, HH, BB);    // 32 x 4 x 8
    attn_kernel<<<gB, 256>>>(mask);

    dim3 gC(DD/64, LL/64, BB); // 2 x 32 x 8
    out_kernel<<<gC, 256>>>(Wo, out);
}